// round 3
// baseline (speedup 1.0000x reference)
#include <cuda_runtime.h>
#include <math.h>

#define NN    20000
#define EE    320000
#define CC    32
#define SS    64
#define GG    64
#define NRADI 8
#define HR    64
#define OUTS  16
#define HHEAD 64
#define RCUTF 5.0f

// ---------------- scratch (device globals) ----------------------------------
__device__ float g_rw[2][EE * CC];    // per-edge radial weights, both layers
__device__ float g_hbuf[2][NN * CC];  // ping-pong node features
__device__ int   g_rowptr[NN + 1];    // CSR row pointers (by receiver)
__device__ int   g_cursor[NN];        // counts, then scatter cursors
__device__ int   g_eorder[EE];        // edge ids grouped by receiver
__device__ float g_gsum[GG];
__device__ float g_gcnt[GG];

// ---------------- init: h = species_embed[species], zero counters -----------
__global__ void k_init(const int* __restrict__ species, const float* __restrict__ emb) {
    int i = blockIdx.x * blockDim.x + threadIdx.x;
    if (i < NN * CC) {
        int n = i >> 5, c = i & 31;
        g_hbuf[0][i] = emb[species[n] * CC + c];
    }
    if (i < NN) g_cursor[i] = 0;
    if (i < GG) { g_gsum[i] = 0.f; g_gcnt[i] = 0.f; }
}

// ---------------- CSR build --------------------------------------------------
__global__ void k_hist(const int* __restrict__ receivers) {
    int e = blockIdx.x * blockDim.x + threadIdx.x;
    if (e < EE) atomicAdd(&g_cursor[receivers[e]], 1);
}

// one-block exclusive scan over 20000 counts; writes rowptr and resets cursor
__global__ void __launch_bounds__(1024) k_scan() {
    __shared__ int s[1024];
    int tid = threadIdx.x;
    const int CHUNK = 20;                 // 1024*20 = 20480 >= 20000
    int base = tid * CHUNK;
    int sum = 0;
    for (int i = 0; i < CHUNK; i++) {
        int idx = base + i;
        if (idx < NN) sum += g_cursor[idx];
    }
    s[tid] = sum;
    __syncthreads();
    for (int off = 1; off < 1024; off <<= 1) {
        int v = (tid >= off) ? s[tid - off] : 0;
        __syncthreads();
        s[tid] += v;
        __syncthreads();
    }
    int run = (tid == 0) ? 0 : s[tid - 1];
    for (int i = 0; i < CHUNK; i++) {
        int idx = base + i;
        if (idx < NN) {
            int v = g_cursor[idx];
            g_rowptr[idx] = run;
            g_cursor[idx] = run;   // scatter cursor starts at row offset
            run += v;
        }
    }
    if (tid == 0) g_rowptr[NN] = EE;
}

__global__ void k_scatter(const int* __restrict__ receivers) {
    int e = blockIdx.x * blockDim.x + threadIdx.x;
    if (e < EE) {
        int pos = atomicAdd(&g_cursor[receivers[e]], 1);
        g_eorder[pos] = e;
    }
}

// ---------------- per-edge: bessel -> silu(.@W1) -> @W2 (both layers) -------
__global__ void __launch_bounds__(128) k_edge(const float* __restrict__ vectors,
                                              const float* __restrict__ w_r1,
                                              const float* __restrict__ b_r1,
                                              const float* __restrict__ w_r2) {
    __shared__ float s_w1[HR * NRADI];  // transposed: [j][k]
    __shared__ float s_b1[HR];
    __shared__ float s_w2[HR * 64];     // [j][d]; d<32 -> layer0, d>=32 -> layer1
    int tid = threadIdx.x;
    for (int i = tid; i < HR * NRADI; i += 128) {
        int j = i / NRADI, k = i % NRADI;
        s_w1[i] = w_r1[k * HR + j];
    }
    for (int i = tid; i < HR; i += 128) s_b1[i] = b_r1[i];
    for (int i = tid; i < HR * 64; i += 128) {
        int j = i >> 6, d = i & 63;
        int li = d >> 5;
        s_w2[i] = w_r2[(li * HR + j) * 96 + (d & 31)];
    }
    __syncthreads();

    int e = blockIdx.x * 128 + tid;
    if (e >= EE) return;

    float vx = vectors[3 * e + 0];
    float vy = vectors[3 * e + 1];
    float vz = vectors[3 * e + 2];
    float r2 = vx * vx + vy * vy + vz * vz;
    float r  = (r2 == 0.f) ? 0.f : sqrtf(r2);
    float rs = fmaxf(r, 1e-6f);
    float u  = fminf(r * (1.f / RCUTF), 1.f);
    float omu = 1.f - u;
    float env = omu * omu * (1.f + 2.f * u);
    float pref = 0.6324555320336759f * env / rs;  // sqrt(2/RCUT)

    // sin(k*theta) via Chebyshev recurrence
    float theta = (3.14159265358979323846f / RCUTF) * rs;
    float s1, c1;
    sincosf(theta, &s1, &c1);
    float twoc = 2.f * c1;
    float bes[NRADI];
    float sprev = 0.f, scur = s1;
    bes[0] = pref * scur;
#pragma unroll
    for (int k = 1; k < NRADI; k++) {
        float snext = twoc * scur - sprev;
        sprev = scur; scur = snext;
        bes[k] = pref * scur;
    }

    float acc[64];
#pragma unroll
    for (int d = 0; d < 64; d++) acc[d] = 0.f;

#pragma unroll 4
    for (int j = 0; j < HR; j++) {
        const float4* w1r = (const float4*)&s_w1[j * NRADI];
        float4 a = w1r[0], b = w1r[1];
        float t = s_b1[j]
                + bes[0] * a.x + bes[1] * a.y + bes[2] * a.z + bes[3] * a.w
                + bes[4] * b.x + bes[5] * b.y + bes[6] * b.z + bes[7] * b.w;
        float rj = t * (1.f / (1.f + __expf(-t)));  // silu
        const float4* w2r = (const float4*)&s_w2[j * 64];
#pragma unroll
        for (int q = 0; q < 16; q++) {
            float4 w = w2r[q];
            acc[4 * q + 0] += rj * w.x;
            acc[4 * q + 1] += rj * w.y;
            acc[4 * q + 2] += rj * w.z;
            acc[4 * q + 3] += rj * w.w;
        }
    }

    float4* o0 = (float4*)&g_rw[0][e * CC];
    float4* o1 = (float4*)&g_rw[1][e * CC];
#pragma unroll
    for (int q = 0; q < 8; q++) {
        o0[q] = make_float4(acc[4 * q + 0], acc[4 * q + 1], acc[4 * q + 2], acc[4 * q + 3]);
        o1[q] = make_float4(acc[32 + 4 * q + 0], acc[32 + 4 * q + 1],
                            acc[32 + 4 * q + 2], acc[32 + 4 * q + 3]);
    }
}

// ---------------- fused layer: gather-aggregate + node update ---------------
// One warp per receiver node; lane = channel c. No atomics.
// acc[c] = sum_{e in CSR(n)} rw[li][e][c] * h_in[snd(e)][c]
// h_out[n] = acc @ Wmix0 + h_in[n] @ Wsc[sp] + h_in[n]
__global__ void __launch_bounds__(256) k_layer(const int* __restrict__ senders,
                                               const int* __restrict__ species,
                                               const float* __restrict__ w_mix,
                                               const float* __restrict__ w_sc,
                                               int li,
                                               const float* __restrict__ hin,
                                               float* __restrict__ hout) {
    int warp = (blockIdx.x * 256 + threadIdx.x) >> 5;
    if (warp >= NN) return;
    int n = warp;
    int lane = threadIdx.x & 31;

    int start = g_rowptr[n];
    int end   = g_rowptr[n + 1];

    float acc = 0.f;
    const float* rwl = &g_rw[li][0];
    for (int base = start; base < end; base += 32) {
        int cnt = min(32, end - base);
        int eid = 0, snd = 0;
        if (lane < cnt) {
            eid = __ldg(&g_eorder[base + lane]);
            snd = __ldg(&senders[eid]);
        }
#pragma unroll 4
        for (int j = 0; j < cnt; j++) {
            int e = __shfl_sync(0xffffffffu, eid, j);
            int s = __shfl_sync(0xffffffffu, snd, j);
            acc += __ldg(&rwl[e * CC + lane]) * __ldg(&hin[s * CC + lane]);
        }
    }

    // node update (c-group g, output-quad d4 decomposition)
    int g  = lane >> 3;
    int d4 = lane & 7;
    int sp = __ldg(&species[n]);
    const float* wm = w_mix + li * 3 * CC * CC;           // w_mix[li][0]
    const float* ws = w_sc + (li * SS + sp) * CC * CC;    // w_sc[li][sp]
    float hv = hin[n * CC + lane];

    float ax = 0.f, ay = 0.f, az = 0.f, aw = 0.f;
#pragma unroll
    for (int cc = 0; cc < 8; cc++) {
        int c = g * 8 + cc;
        float a  = __shfl_sync(0xffffffffu, acc, c);
        float hc = __shfl_sync(0xffffffffu, hv, c);
        float4 wmv = __ldg(((const float4*)(wm + c * CC)) + d4);
        float4 wsv = __ldg(((const float4*)(ws + c * CC)) + d4);
        ax += a * wmv.x + hc * wsv.x;
        ay += a * wmv.y + hc * wsv.y;
        az += a * wmv.z + hc * wsv.z;
        aw += a * wmv.w + hc * wsv.w;
    }
#pragma unroll
    for (int off = 8; off <= 16; off <<= 1) {
        ax += __shfl_xor_sync(0xffffffffu, ax, off);
        ay += __shfl_xor_sync(0xffffffffu, ay, off);
        az += __shfl_xor_sync(0xffffffffu, az, off);
        aw += __shfl_xor_sync(0xffffffffu, aw, off);
    }
    if (g == 0) {
        float4 hq = __ldg(((const float4*)(hin + n * CC)) + d4);
        ((float4*)(hout + n * CC))[d4] =
            make_float4(ax + hq.x, ay + hq.y, az + hq.z, aw + hq.w);
    }
}

// ---------------- readout + LN + MLP head + per-graph pooling ---------------
__device__ __forceinline__ float fast_tanh(float x) {
    float e = __expf(2.f * x);
    return 1.f - 2.f / (e + 1.f);
}

__global__ void __launch_bounds__(128) k_head(const int* __restrict__ graph_id,
                                              const float* __restrict__ hfin,
                                              const float* __restrict__ w_ro,
                                              const float* __restrict__ gamma,
                                              const float* __restrict__ beta,
                                              const float* __restrict__ w_h1,
                                              const float* __restrict__ b_h1,
                                              const float* __restrict__ w_h2,
                                              const float* __restrict__ b_h2) {
    __shared__ float s_ro[CC * OUTS];
    __shared__ float s_h1[OUTS * HHEAD];
    __shared__ float s_h2[HHEAD];
    __shared__ float s_bh1[HHEAD];
    __shared__ float s_g[OUTS], s_b[OUTS];
    __shared__ float sbin[GG];
    __shared__ float scnt[GG];
    int tid = threadIdx.x;
    for (int i = tid; i < CC * OUTS; i += 128) s_ro[i] = w_ro[i];
    for (int i = tid; i < OUTS * HHEAD; i += 128) s_h1[i] = w_h1[i];
    for (int i = tid; i < HHEAD; i += 128) { s_h2[i] = w_h2[i]; s_bh1[i] = b_h1[i]; }
    for (int i = tid; i < OUTS; i += 128) { s_g[i] = gamma[i]; s_b[i] = beta[i]; }
    for (int i = tid; i < GG; i += 128) { sbin[i] = 0.f; scnt[i] = 0.f; }
    __syncthreads();

    int n = blockIdx.x * 128 + tid;
    if (n < NN) {
        float hrow[CC];
        const float4* hr = (const float4*)&hfin[n * CC];
#pragma unroll
        for (int q = 0; q < 8; q++) {
            float4 v = hr[q];
            hrow[4 * q + 0] = v.x; hrow[4 * q + 1] = v.y;
            hrow[4 * q + 2] = v.z; hrow[4 * q + 3] = v.w;
        }
        float ro[OUTS];
#pragma unroll
        for (int d = 0; d < OUTS; d++) {
            float s = 0.f;
#pragma unroll
            for (int c = 0; c < CC; c++) s += hrow[c] * s_ro[c * OUTS + d];
            ro[d] = s;
        }
        float mu = 0.f;
#pragma unroll
        for (int d = 0; d < OUTS; d++) mu += ro[d];
        mu *= (1.f / OUTS);
        float var = 0.f;
#pragma unroll
        for (int d = 0; d < OUTS; d++) { float x = ro[d] - mu; var += x * x; }
        var *= (1.f / OUTS);
        float inv = rsqrtf(var + 1e-6f);
        float nrm[OUTS];
#pragma unroll
        for (int d = 0; d < OUTS; d++) nrm[d] = (ro[d] - mu) * inv * s_g[d] + s_b[d];

        float outv = 0.f;
#pragma unroll 4
        for (int j = 0; j < HHEAD; j++) {
            float t2 = s_bh1[j];
#pragma unroll
            for (int d = 0; d < OUTS; d++) t2 += nrm[d] * s_h1[d * HHEAD + j];
            float x3 = t2 * t2 * t2;
            float tg = fast_tanh(0.7978845608028654f * (t2 + 0.044715f * x3));
            float gel = 0.5f * t2 * (1.f + tg);
            outv += gel * s_h2[j];
        }
        outv += b_h2[0];
        int gid = __ldg(&graph_id[n]);
        atomicAdd(&sbin[gid], outv);
        atomicAdd(&scnt[gid], 1.f);
    }
    __syncthreads();
    for (int i = tid; i < GG; i += 128) {
        if (sbin[i] != 0.f) atomicAdd(&g_gsum[i], sbin[i]);
        if (scnt[i] != 0.f) atomicAdd(&g_gcnt[i], scnt[i]);
    }
}

// ---------------- finalize ---------------------------------------------------
__global__ void k_final(const float* __restrict__ scale, const float* __restrict__ shift,
                        float* __restrict__ out) {
    int g = threadIdx.x;
    if (g < GG) {
        float c = g_gcnt[g];
        out[g] = g_gsum[g] / fmaxf(c, 1.f) * scale[0] + shift[0];
    }
}

extern "C" void kernel_launch(void* const* d_in, const int* in_sizes, int n_in,
                              void* d_out, int out_size) {
    (void)in_sizes; (void)n_in; (void)out_size;
    const float* vectors   = (const float*)d_in[0];
    const int*   species   = (const int*)d_in[1];
    const int*   senders   = (const int*)d_in[2];
    const int*   receivers = (const int*)d_in[3];
    const int*   graph_id  = (const int*)d_in[4];
    const float* emb       = (const float*)d_in[5];
    const float* w_r1      = (const float*)d_in[6];
    const float* b_r1      = (const float*)d_in[7];
    const float* w_r2      = (const float*)d_in[8];
    const float* w_mix     = (const float*)d_in[9];
    const float* w_sc      = (const float*)d_in[10];
    const float* w_ro      = (const float*)d_in[11];
    const float* gamma     = (const float*)d_in[12];
    const float* beta      = (const float*)d_in[13];
    const float* w_h1      = (const float*)d_in[14];
    const float* b_h1      = (const float*)d_in[15];
    const float* w_h2      = (const float*)d_in[16];
    const float* b_h2      = (const float*)d_in[17];
    const float* scale     = (const float*)d_in[18];
    const float* shift     = (const float*)d_in[19];
    float* out = (float*)d_out;

    float* h0; float* h1;
    cudaGetSymbolAddress((void**)&h0, g_hbuf);  // base of g_hbuf[0]
    h1 = h0 + NN * CC;

    k_init<<<(NN * CC + 255) / 256, 256>>>(species, emb);
    k_hist<<<(EE + 255) / 256, 256>>>(receivers);
    k_scan<<<1, 1024>>>();
    k_scatter<<<(EE + 255) / 256, 256>>>(receivers);
    k_edge<<<(EE + 127) / 128, 128>>>(vectors, w_r1, b_r1, w_r2);
    k_layer<<<(NN * 32 + 255) / 256, 256>>>(senders, species, w_mix, w_sc, 0, h0, h1);
    k_layer<<<(NN * 32 + 255) / 256, 256>>>(senders, species, w_mix, w_sc, 1, h1, h0);
    k_head<<<(NN + 127) / 128, 128>>>(graph_id, h0, w_ro, gamma, beta, w_h1, b_h1, w_h2, b_h2);
    k_final<<<1, 64>>>(scale, shift, out);
}

// round 4
// speedup vs baseline: 2.7491x; 2.7491x over previous
#include <cuda_runtime.h>
#include <math.h>

#define NN    20000
#define EE    320000
#define CC    32
#define SS    64
#define GG    64
#define NRADI 8
#define HR    64
#define OUTS  16
#define HHEAD 64
#define RCUTF 5.0f
#define TABN  8192          // table knots over r in [0, RCUT]

// ---------------- scratch (device globals) ----------------------------------
__device__ float g_tab[TABN * 64];   // radial table: [knot][li*32 + c]  (2 MB)
__device__ float g_rt[EE];           // per-edge scaled r (table coordinate)
__device__ float g_h[NN * CC];       // node features
__device__ float g_agg[NN * CC];     // message aggregation
__device__ float g_gsum[GG];
__device__ float g_gcnt[GG];

// ---------------- init: h = emb[species], agg=0, per-edge table coord -------
__global__ void k_init(const int* __restrict__ species, const float* __restrict__ emb,
                       const float* __restrict__ vectors) {
    int i = blockIdx.x * blockDim.x + threadIdx.x;
    if (i < NN * CC) {
        int n = i >> 5, c = i & 31;
        g_h[i] = emb[species[n] * CC + c];
        g_agg[i] = 0.f;
    }
    if (i < EE) {
        float vx = vectors[3 * i + 0];
        float vy = vectors[3 * i + 1];
        float vz = vectors[3 * i + 2];
        float r2 = vx * vx + vy * vy + vz * vz;
        float r  = (r2 == 0.f) ? 0.f : sqrtf(r2);
        float u  = r * ((float)(TABN - 1) / RCUTF);
        g_rt[i] = fminf(u, (float)(TABN - 1) - 1e-3f);
    }
    if (i < GG) { g_gsum[i] = 0.f; g_gcnt[i] = 0.f; }
}

// ---------------- build radial table: F(r) for TABN knots -------------------
// One thread per knot; same math as the reference per-edge network.
__global__ void __launch_bounds__(128) k_table(const float* __restrict__ w_r1,
                                               const float* __restrict__ b_r1,
                                               const float* __restrict__ w_r2) {
    __shared__ float s_w1[HR * NRADI];  // transposed [j][k]
    __shared__ float s_b1[HR];
    __shared__ float s_w2[HR * 64];     // [j][d]; d<32 layer0, d>=32 layer1
    int tid = threadIdx.x;
    for (int i = tid; i < HR * NRADI; i += 128) {
        int j = i / NRADI, k = i % NRADI;
        s_w1[i] = w_r1[k * HR + j];
    }
    for (int i = tid; i < HR; i += 128) s_b1[i] = b_r1[i];
    for (int i = tid; i < HR * 64; i += 128) {
        int j = i >> 6, d = i & 63;
        int li = d >> 5;
        s_w2[i] = w_r2[(li * HR + j) * 96 + (d & 31)];
    }
    __syncthreads();

    int knot = blockIdx.x * 128 + tid;
    if (knot >= TABN) return;

    float r  = (float)knot * (RCUTF / (float)(TABN - 1));
    float rs = fmaxf(r, 1e-6f);
    float u  = fminf(r * (1.f / RCUTF), 1.f);
    float omu = 1.f - u;
    float env = omu * omu * (1.f + 2.f * u);
    float pref = 0.6324555320336759f * env / rs;  // sqrt(2/RCUT)

    float theta = (3.14159265358979323846f / RCUTF) * rs;
    float s1, c1;
    sincosf(theta, &s1, &c1);
    float twoc = 2.f * c1;
    float bes[NRADI];
    float sprev = 0.f, scur = s1;
    bes[0] = pref * scur;
#pragma unroll
    for (int k = 1; k < NRADI; k++) {
        float snext = twoc * scur - sprev;
        sprev = scur; scur = snext;
        bes[k] = pref * scur;
    }

    float acc[64];
#pragma unroll
    for (int d = 0; d < 64; d++) acc[d] = 0.f;

#pragma unroll 4
    for (int j = 0; j < HR; j++) {
        const float4* w1r = (const float4*)&s_w1[j * NRADI];
        float4 a = w1r[0], b = w1r[1];
        float t = s_b1[j]
                + bes[0] * a.x + bes[1] * a.y + bes[2] * a.z + bes[3] * a.w
                + bes[4] * b.x + bes[5] * b.y + bes[6] * b.z + bes[7] * b.w;
        float rj = t / (1.f + expf(-t));  // silu (accurate exp; tiny kernel)
        const float4* w2r = (const float4*)&s_w2[j * 64];
#pragma unroll
        for (int q = 0; q < 16; q++) {
            float4 w = w2r[q];
            acc[4 * q + 0] += rj * w.x;
            acc[4 * q + 1] += rj * w.y;
            acc[4 * q + 2] += rj * w.z;
            acc[4 * q + 3] += rj * w.w;
        }
    }

    float4* orow = (float4*)&g_tab[knot * 64];
#pragma unroll
    for (int q = 0; q < 16; q++)
        orow[q] = make_float4(acc[4 * q + 0], acc[4 * q + 1], acc[4 * q + 2], acc[4 * q + 3]);
}

// ---------------- message + scatter with fused table lookup -----------------
// 8 threads per edge; rw = lerp(table) ; agg[recv] += rw * h[send] via v4 RED.
__global__ void k_msg(const int* __restrict__ senders, const int* __restrict__ receivers,
                      int li) {
    int t = blockIdx.x * blockDim.x + threadIdx.x;
    int e = t >> 3;
    if (e >= EE) return;
    int q = t & 7;
    float u = __ldg(&g_rt[e]);
    int i = (int)u;
    float f = u - (float)i;
    const float* base = g_tab + i * 64 + li * 32 + q * 4;
    float4 v0 = __ldg((const float4*)base);
    float4 v1 = __ldg((const float4*)(base + 64));
    float rwx = v0.x + f * (v1.x - v0.x);
    float rwy = v0.y + f * (v1.y - v0.y);
    float rwz = v0.z + f * (v1.z - v0.z);
    float rww = v0.w + f * (v1.w - v0.w);

    int snd = __ldg(&senders[e]);
    int rcv = __ldg(&receivers[e]);
    float4 hv = __ldg(((const float4*)g_h) + snd * 8 + q);
    float mx = rwx * hv.x, my = rwy * hv.y, mz = rwz * hv.z, mw = rww * hv.w;
    float* dst = &g_agg[rcv * CC + q * 4];
    asm volatile("red.global.add.v4.f32 [%0], {%1,%2,%3,%4};"
                 :: "l"(dst), "f"(mx), "f"(my), "f"(mz), "f"(mw) : "memory");
}

// ---------------- node update: h = agg@Wmix0 + h@Wsc[sp] + h; agg = 0 -------
__global__ void __launch_bounds__(256) k_update(const int* __restrict__ species,
                                                const float* __restrict__ w_mix,
                                                const float* __restrict__ w_sc, int li) {
    __shared__ float s_wm[CC * CC];
    int tid = threadIdx.x;
    const float* wm = w_mix + li * 3 * CC * CC;  // w_mix[li][0]
    for (int i = tid; i < CC * CC; i += 256) s_wm[i] = wm[i];
    __syncthreads();

    int t = blockIdx.x * 256 + tid;
    int n = t >> 5;
    if (n >= NN) return;
    int lane = t & 31;
    int g  = lane >> 3;   // c-group: c in [8g, 8g+8)
    int d4 = lane & 7;    // output quad
    int sp = __ldg(&species[n]);
    const float* ws = w_sc + (li * SS + sp) * CC * CC;

    float aggv = g_agg[n * CC + lane];
    float hv   = g_h[n * CC + lane];

    float ax = 0.f, ay = 0.f, az = 0.f, aw = 0.f;
#pragma unroll
    for (int cc = 0; cc < 8; cc++) {
        int c = g * 8 + cc;
        float a  = __shfl_sync(0xffffffffu, aggv, c);
        float hc = __shfl_sync(0xffffffffu, hv, c);
        float4 wmv = ((const float4*)(s_wm + c * CC))[d4];
        float4 wsv = __ldg(((const float4*)(ws + c * CC)) + d4);
        ax += a * wmv.x + hc * wsv.x;
        ay += a * wmv.y + hc * wsv.y;
        az += a * wmv.z + hc * wsv.z;
        aw += a * wmv.w + hc * wsv.w;
    }
#pragma unroll
    for (int off = 8; off <= 16; off <<= 1) {
        ax += __shfl_xor_sync(0xffffffffu, ax, off);
        ay += __shfl_xor_sync(0xffffffffu, ay, off);
        az += __shfl_xor_sync(0xffffffffu, az, off);
        aw += __shfl_xor_sync(0xffffffffu, aw, off);
    }
    if (g == 0) {
        float4 hq = ((const float4*)&g_h[n * CC])[d4];
        ((float4*)&g_h[n * CC])[d4] =
            make_float4(ax + hq.x, ay + hq.y, az + hq.z, aw + hq.w);
    }
    g_agg[n * CC + lane] = 0.f;   // ready for next layer
}

// ---------------- readout + LN + MLP head + per-graph pooling ---------------
__device__ __forceinline__ float fast_tanh(float x) {
    float e = __expf(2.f * x);
    return 1.f - 2.f / (e + 1.f);
}

__global__ void __launch_bounds__(128) k_head(const int* __restrict__ graph_id,
                                              const float* __restrict__ w_ro,
                                              const float* __restrict__ gamma,
                                              const float* __restrict__ beta,
                                              const float* __restrict__ w_h1,
                                              const float* __restrict__ b_h1,
                                              const float* __restrict__ w_h2,
                                              const float* __restrict__ b_h2) {
    __shared__ float s_ro[CC * OUTS];
    __shared__ float s_h1[OUTS * HHEAD];
    __shared__ float s_h2[HHEAD];
    __shared__ float s_bh1[HHEAD];
    __shared__ float s_g[OUTS], s_b[OUTS];
    __shared__ float sbin[GG];
    __shared__ float scnt[GG];
    int tid = threadIdx.x;
    for (int i = tid; i < CC * OUTS; i += 128) s_ro[i] = w_ro[i];
    for (int i = tid; i < OUTS * HHEAD; i += 128) s_h1[i] = w_h1[i];
    for (int i = tid; i < HHEAD; i += 128) { s_h2[i] = w_h2[i]; s_bh1[i] = b_h1[i]; }
    for (int i = tid; i < OUTS; i += 128) { s_g[i] = gamma[i]; s_b[i] = beta[i]; }
    for (int i = tid; i < GG; i += 128) { sbin[i] = 0.f; scnt[i] = 0.f; }
    __syncthreads();

    int n = blockIdx.x * 128 + tid;
    if (n < NN) {
        float hrow[CC];
        const float4* hr = (const float4*)&g_h[n * CC];
#pragma unroll
        for (int q = 0; q < 8; q++) {
            float4 v = hr[q];
            hrow[4 * q + 0] = v.x; hrow[4 * q + 1] = v.y;
            hrow[4 * q + 2] = v.z; hrow[4 * q + 3] = v.w;
        }
        float ro[OUTS];
#pragma unroll
        for (int d = 0; d < OUTS; d++) {
            float s = 0.f;
#pragma unroll
            for (int c = 0; c < CC; c++) s += hrow[c] * s_ro[c * OUTS + d];
            ro[d] = s;
        }
        float mu = 0.f;
#pragma unroll
        for (int d = 0; d < OUTS; d++) mu += ro[d];
        mu *= (1.f / OUTS);
        float var = 0.f;
#pragma unroll
        for (int d = 0; d < OUTS; d++) { float x = ro[d] - mu; var += x * x; }
        var *= (1.f / OUTS);
        float inv = rsqrtf(var + 1e-6f);
        float nrm[OUTS];
#pragma unroll
        for (int d = 0; d < OUTS; d++) nrm[d] = (ro[d] - mu) * inv * s_g[d] + s_b[d];

        float outv = 0.f;
#pragma unroll 4
        for (int j = 0; j < HHEAD; j++) {
            float t2 = s_bh1[j];
#pragma unroll
            for (int d = 0; d < OUTS; d++) t2 += nrm[d] * s_h1[d * HHEAD + j];
            float x3 = t2 * t2 * t2;
            float tg = fast_tanh(0.7978845608028654f * (t2 + 0.044715f * x3));
            float gel = 0.5f * t2 * (1.f + tg);
            outv += gel * s_h2[j];
        }
        outv += b_h2[0];
        int gid = __ldg(&graph_id[n]);
        atomicAdd(&sbin[gid], outv);
        atomicAdd(&scnt[gid], 1.f);
    }
    __syncthreads();
    for (int i = tid; i < GG; i += 128) {
        if (sbin[i] != 0.f) atomicAdd(&g_gsum[i], sbin[i]);
        if (scnt[i] != 0.f) atomicAdd(&g_gcnt[i], scnt[i]);
    }
}

// ---------------- finalize ---------------------------------------------------
__global__ void k_final(const float* __restrict__ scale, const float* __restrict__ shift,
                        float* __restrict__ out) {
    int g = threadIdx.x;
    if (g < GG) {
        float c = g_gcnt[g];
        out[g] = g_gsum[g] / fmaxf(c, 1.f) * scale[0] + shift[0];
    }
}

extern "C" void kernel_launch(void* const* d_in, const int* in_sizes, int n_in,
                              void* d_out, int out_size) {
    (void)in_sizes; (void)n_in; (void)out_size;
    const float* vectors   = (const float*)d_in[0];
    const int*   species   = (const int*)d_in[1];
    const int*   senders   = (const int*)d_in[2];
    const int*   receivers = (const int*)d_in[3];
    const int*   graph_id  = (const int*)d_in[4];
    const float* emb       = (const float*)d_in[5];
    const float* w_r1      = (const float*)d_in[6];
    const float* b_r1      = (const float*)d_in[7];
    const float* w_r2      = (const float*)d_in[8];
    const float* w_mix     = (const float*)d_in[9];
    const float* w_sc      = (const float*)d_in[10];
    const float* w_ro      = (const float*)d_in[11];
    const float* gamma     = (const float*)d_in[12];
    const float* beta      = (const float*)d_in[13];
    const float* w_h1      = (const float*)d_in[14];
    const float* b_h1      = (const float*)d_in[15];
    const float* w_h2      = (const float*)d_in[16];
    const float* b_h2      = (const float*)d_in[17];
    const float* scale     = (const float*)d_in[18];
    const float* shift     = (const float*)d_in[19];
    float* out = (float*)d_out;

    k_init<<<(NN * CC + 255) / 256, 256>>>(species, emb, vectors);
    k_table<<<(TABN + 127) / 128, 128>>>(w_r1, b_r1, w_r2);
    for (int li = 0; li < 2; li++) {
        k_msg<<<(EE * 8 + 255) / 256, 256>>>(senders, receivers, li);
        k_update<<<(NN * CC + 255) / 256, 256>>>(species, w_mix, w_sc, li);
    }
    k_head<<<(NN + 127) / 128, 128>>>(graph_id, w_ro, gamma, beta, w_h1, b_h1, w_h2, b_h2);
    k_final<<<1, 64>>>(scale, shift, out);
}